// round 16
// baseline (speedup 1.0000x reference)
#include <cuda_runtime.h>
#include <cuda_fp16.h>
#include <math_constants.h>

#define N_NODES 65536
#define N_EDGES 1048576
#define IN_F 128
#define HID 64
#define L2E 1.44269504088896f   // log2(e)
#define LN2 0.69314718055995f   // 1/log2(e)

// ---------------- scratch (device globals; no allocation allowed) ----------
__device__ __half g_h0[N_NODES * HID];  // 8 MB, fp16 node features ping
__device__ __half g_h1[N_NODES * HID];  // 8 MB, pong
__device__ float  g_rnA[N_NODES];       // log2e / max(||h||, eps)  (pre-scaled!)
__device__ float  g_rnB[N_NODES];       // pong
__device__ int    g_deg[N_NODES];       // zeroed by scanF each pass
__device__ int    g_off[N_NODES + 1];
__device__ int    g_cur[N_NODES];
__device__ int    g_bsum[256];          // chunk sums; zeroed by projscatter
__device__ int    g_csr[N_EDGES];       // src node id, grouped by dst

// ---------------- packed f32x2 helpers (sm_103a; inline PTX only) ----------
#define MUL2(d, a, b) \
    asm("mul.rn.f32x2 %0, %1, %2;" : "=l"(d) : "l"(a), "l"(b))
#define FMA2(d, a, b, c) \
    asm("fma.rn.f32x2 %0, %1, %2, %3;" : "=l"(d) : "l"(a), "l"(b), "l"(c))

__device__ __forceinline__ unsigned long long h2f2(unsigned h2v) {
    float2 t = __half22float2(*reinterpret_cast<const __half2*>(&h2v));
    unsigned long long p;
    asm("mov.b64 %0, {%1, %2};"
        : "=l"(p) : "r"(__float_as_uint(t.x)), "r"(__float_as_uint(t.y)));
    return p;
}
__device__ __forceinline__ void unpk2(unsigned long long p, float& lo, float& hi) {
    unsigned a, b;
    asm("mov.b64 {%0, %1}, %2;" : "=r"(a), "=r"(b) : "l"(p));
    lo = __uint_as_float(a); hi = __uint_as_float(b);
}
__device__ __forceinline__ float ex2f(float x) {
    float y;
    asm("ex2.approx.ftz.f32 %0, %1;" : "=f"(y) : "f"(x));
    return y;
}

// ---------------- launch 1: histogram, 8 edges/thread ----------------------
__global__ __launch_bounds__(256) void hist_kernel(
    const int* __restrict__ dst, int* __restrict__ deg, int* __restrict__ bsum)
{
    __shared__ int sc[256];
    int t = threadIdx.x;
    sc[t] = 0;
    __syncthreads();
    int i = blockIdx.x * 256 + t;
    int4 d0 = __ldg((const int4*)dst + 2 * i);
    int4 d1 = __ldg((const int4*)dst + 2 * i + 1);
    atomicAdd(deg + d0.x, 1); atomicAdd(deg + d0.y, 1);
    atomicAdd(deg + d0.z, 1); atomicAdd(deg + d0.w, 1);
    atomicAdd(deg + d1.x, 1); atomicAdd(deg + d1.y, 1);
    atomicAdd(deg + d1.z, 1); atomicAdd(deg + d1.w, 1);
    atomicAdd(sc + (d0.x >> 8), 1); atomicAdd(sc + (d0.y >> 8), 1);
    atomicAdd(sc + (d0.z >> 8), 1); atomicAdd(sc + (d0.w >> 8), 1);
    atomicAdd(sc + (d1.x >> 8), 1); atomicAdd(sc + (d1.y >> 8), 1);
    atomicAdd(sc + (d1.z >> 8), 1); atomicAdd(sc + (d1.w >> 8), 1);
    __syncthreads();
    int v = sc[t];
    if (v) atomicAdd(bsum + t, v);      // 256 spread addresses per block
}

// ---------------- launch 2: fused scan (block-local + chunk) + deg reset ---
__global__ __launch_bounds__(256) void scanF_kernel(
    const int* __restrict__ bsum, int* __restrict__ deg,
    int* __restrict__ off, int* __restrict__ cur)
{
    __shared__ int s[256];
    __shared__ int sb[256];
    int t = threadIdx.x;
    int b = blockIdx.x;
    int g = b * 256 + t;
    int d = deg[g];
    deg[g] = 0;                          // reset for next graph replay
    s[t]  = d;
    sb[t] = bsum[t];
    __syncthreads();
#pragma unroll
    for (int o = 1; o < 256; o <<= 1) {
        int v1 = (t >= o) ? s[t - o]  : 0;
        int v2 = (t >= o) ? sb[t - o] : 0;
        __syncthreads();
        s[t] += v1; sb[t] += v2;
        __syncthreads();
    }
    int excl_blk = sb[b] - bsum[b];      // exclusive chunk prefix
    int v = (s[t] - d) + excl_blk;       // global exclusive offset
    off[g] = v;
    cur[g] = v;
    if (g == 0) off[N_NODES] = N_EDGES;
}

// ---------------- launch 3: scatter (2 e/thread) + proj GEMM (32 rows) -----
__global__ __launch_bounds__(256) void projscatter_kernel(
    const int* __restrict__ src, const int* __restrict__ dst,
    int* __restrict__ cur, int* __restrict__ csr, int* __restrict__ bsum,
    const float* __restrict__ feat, const float* __restrict__ W1,
    const float* __restrict__ b1, __half* __restrict__ out,
    float* __restrict__ rn)
{
    __shared__ float sWt[HID][132];       // 33.8 KB, padded
    int tid = threadIdx.x;

    // --- scatter: 2 edges per thread (grid 2048 * 512 = N_EDGES) ---
    {
        int e0 = blockIdx.x * 512 + tid;
        int e1 = e0 + 256;
        int d0 = __ldg(dst + e0), d1 = __ldg(dst + e1);
        int v0 = __ldg(src + e0), v1 = __ldg(src + e1);
        int p0 = atomicAdd(cur + d0, 1);
        int p1 = atomicAdd(cur + d1, 1);
        csr[p0] = v0;
        csr[p1] = v1;
    }
    if (blockIdx.x == 0) bsum[tid] = 0;   // reset chunk sums for next replay

    // --- stage transposed W1 tile ---
    for (int i = tid; i < IN_F * HID; i += 256) {
        int k = i >> 6, j = i & 63;
        sWt[j][k] = W1[i];
    }
    __syncthreads();

    int row0 = blockIdx.x * 32;
    int r8 = tid >> 5, c = tid & 31;
    const float4* fr0 = (const float4*)(feat + (row0 + r8     ) * IN_F);
    const float4* fr1 = (const float4*)(feat + (row0 + r8 +  8) * IN_F);
    const float4* fr2 = (const float4*)(feat + (row0 + r8 + 16) * IN_F);
    const float4* fr3 = (const float4*)(feat + (row0 + r8 + 24) * IN_F);
    float bc0 = b1[c], bc1 = b1[c + 32];
    float a00 = bc0, a01 = bc1, a10 = bc0, a11 = bc1;
    float a20 = bc0, a21 = bc1, a30 = bc0, a31 = bc1;
#pragma unroll
    for (int k4 = 0; k4 < IN_F / 4; k4++) {
        float4 w0 = *(const float4*)&sWt[c     ][k4 * 4];
        float4 w1 = *(const float4*)&sWt[c + 32][k4 * 4];
        float4 f0 = __ldg(fr0 + k4);
        float4 f1 = __ldg(fr1 + k4);
        float4 f2 = __ldg(fr2 + k4);
        float4 f3 = __ldg(fr3 + k4);
        a00 = fmaf(f0.x, w0.x, a00); a00 = fmaf(f0.y, w0.y, a00);
        a00 = fmaf(f0.z, w0.z, a00); a00 = fmaf(f0.w, w0.w, a00);
        a01 = fmaf(f0.x, w1.x, a01); a01 = fmaf(f0.y, w1.y, a01);
        a01 = fmaf(f0.z, w1.z, a01); a01 = fmaf(f0.w, w1.w, a01);
        a10 = fmaf(f1.x, w0.x, a10); a10 = fmaf(f1.y, w0.y, a10);
        a10 = fmaf(f1.z, w0.z, a10); a10 = fmaf(f1.w, w0.w, a10);
        a11 = fmaf(f1.x, w1.x, a11); a11 = fmaf(f1.y, w1.y, a11);
        a11 = fmaf(f1.z, w1.z, a11); a11 = fmaf(f1.w, w1.w, a11);
        a20 = fmaf(f2.x, w0.x, a20); a20 = fmaf(f2.y, w0.y, a20);
        a20 = fmaf(f2.z, w0.z, a20); a20 = fmaf(f2.w, w0.w, a20);
        a21 = fmaf(f2.x, w1.x, a21); a21 = fmaf(f2.y, w1.y, a21);
        a21 = fmaf(f2.z, w1.z, a21); a21 = fmaf(f2.w, w1.w, a21);
        a30 = fmaf(f3.x, w0.x, a30); a30 = fmaf(f3.y, w0.y, a30);
        a30 = fmaf(f3.z, w0.z, a30); a30 = fmaf(f3.w, w0.w, a30);
        a31 = fmaf(f3.x, w1.x, a31); a31 = fmaf(f3.y, w1.y, a31);
        a31 = fmaf(f3.z, w1.z, a31); a31 = fmaf(f3.w, w1.w, a31);
    }
    a00 = fmaxf(a00, 0.0f); a01 = fmaxf(a01, 0.0f);
    a10 = fmaxf(a10, 0.0f); a11 = fmaxf(a11, 0.0f);
    a20 = fmaxf(a20, 0.0f); a21 = fmaxf(a21, 0.0f);
    a30 = fmaxf(a30, 0.0f); a31 = fmaxf(a31, 0.0f);
    out[(row0 + r8     ) * HID + c     ] = __float2half_rn(a00);
    out[(row0 + r8     ) * HID + c + 32] = __float2half_rn(a01);
    out[(row0 + r8 +  8) * HID + c     ] = __float2half_rn(a10);
    out[(row0 + r8 +  8) * HID + c + 32] = __float2half_rn(a11);
    out[(row0 + r8 + 16) * HID + c     ] = __float2half_rn(a20);
    out[(row0 + r8 + 16) * HID + c + 32] = __float2half_rn(a21);
    out[(row0 + r8 + 24) * HID + c     ] = __float2half_rn(a30);
    out[(row0 + r8 + 24) * HID + c + 32] = __float2half_rn(a31);
    float p0 = a00 * a00 + a01 * a01;
    float p1 = a10 * a10 + a11 * a11;
    float p2 = a20 * a20 + a21 * a21;
    float p3 = a30 * a30 + a31 * a31;
#pragma unroll
    for (int o = 16; o; o >>= 1) {
        p0 += __shfl_xor_sync(0xffffffffu, p0, o);
        p1 += __shfl_xor_sync(0xffffffffu, p1, o);
        p2 += __shfl_xor_sync(0xffffffffu, p2, o);
        p3 += __shfl_xor_sync(0xffffffffu, p3, o);
    }
    if (c == 0) {
        rn[row0 + r8     ] = L2E / fmaxf(sqrtf(p0), 1e-12f);
        rn[row0 + r8 +  8] = L2E / fmaxf(sqrtf(p1), 1e-12f);
        rn[row0 + r8 + 16] = L2E / fmaxf(sqrtf(p2), 1e-12f);
        rn[row0 + r8 + 24] = L2E / fmaxf(sqrtf(p3), 1e-12f);
    }
}

// ---------------- launches 4,5: fused AGNN layer ---------------------------
// 2-slot pipeline (A/B, distance 8 edges) + 48-reg cap -> 5 blocks/SM.
// R9/R10 showed depth>2 buys nothing; occupancy is the binding constraint.
#define PREF(E, SN, RS, RAW)                                              \
    {                                                                     \
        int cidx = min(E, s1m1);                                          \
        SN = __ldg(csr + cidx);                                           \
        RS = __ldg(rn_in + SN);                                           \
        RAW = *(const uint4*)(hh + SN * HID + sub * 8);                   \
    }
#define BODY(E, SN, RS, RAW)                                              \
    {                                                                     \
        unsigned long long f0 = h2f2(RAW.x), f1 = h2f2(RAW.y);            \
        unsigned long long f2 = h2f2(RAW.z), f3 = h2f2(RAW.w);            \
        unsigned long long d2;                                            \
        MUL2(d2, q2[0], f0);                                              \
        FMA2(d2, q2[1], f1, d2);                                          \
        FMA2(d2, q2[2], f2, d2);                                          \
        FMA2(d2, q2[3], f3, d2);                                          \
        float dlo, dhi;                                                   \
        unpk2(d2, dlo, dhi);                                              \
        float dt = dlo + dhi;                                             \
        dt += __shfl_xor_sync(FULL, dt, 1);                               \
        dt += __shfl_xor_sync(FULL, dt, 2);                               \
        dt += __shfl_xor_sync(FULL, dt, 4);                               \
        float w = ex2f(fmaf(dt, RS, mB2));                                \
        w = (E < s1) ? w : 0.0f;                                          \
        ss += w;                                                          \
        unsigned long long w2;                                            \
        asm("mov.b64 %0, {%1, %1};" : "=l"(w2) : "r"(__float_as_uint(w)));\
        FMA2(a2[0], w2, f0, a2[0]);                                       \
        FMA2(a2[1], w2, f1, a2[1]);                                       \
        FMA2(a2[2], w2, f2, a2[2]);                                       \
        FMA2(a2[3], w2, f3, a2[3]);                                       \
        E += 8;                                                           \
        PREF(E, SN, RS, RAW)                                              \
    }

__global__ __launch_bounds__(256, 5) void layer_kernel(
    const int* __restrict__ csr, const int* __restrict__ off,
    const __half* __restrict__ hh, const float* __restrict__ rn_in,
    const float* __restrict__ betas, int layer,
    __half* __restrict__ out_h, float* __restrict__ rn_out)
{
    int node = (blockIdx.x * blockDim.x + threadIdx.x) >> 5;
    int lane = threadIdx.x & 31;
    int qtr  = lane >> 3;
    int sub  = lane & 7;
    const unsigned FULL = 0xffffffffu;

    int s0 = off[node], s1 = off[node + 1];
    int deg = s1 - s0;
    int s1m1 = s1 - 1;
    float beta = __ldg(betas + layer);
    float mB2 = -fabsf(beta) * L2E;               // -log2e * max logit
    unsigned long long q2[4];
    {
        uint4 qraw = *(const uint4*)(hh + node * HID + sub * 8);
        float qs = beta * rn_in[node] * LN2;      // undo the log2e pre-scale
        unsigned long long qs2;
        asm("mov.b64 %0, {%1, %1};" : "=l"(qs2) : "r"(__float_as_uint(qs)));
        q2[0] = h2f2(qraw.x); MUL2(q2[0], q2[0], qs2);
        q2[1] = h2f2(qraw.y); MUL2(q2[1], q2[1], qs2);
        q2[2] = h2f2(qraw.z); MUL2(q2[2], q2[2], qs2);
        q2[3] = h2f2(qraw.w); MUL2(q2[3], q2[3], qs2);
    }

    float ss = 0.0f;
    unsigned long long a2[4] = {0ull, 0ull, 0ull, 0ull};  // packed (0.f, 0.f)

    if (deg > 0) {
        int eA = s0 + qtr, eB = eA + 4;
        int snA, snB; float rsA, rsB; uint4 rawA, rawB;
        PREF(eA, snA, rsA, rawA)
        PREF(eB, snB, rsB, rawB)
        int nIter = (deg + 3) >> 2;               // 4-edge chunks
        while (nIter >= 2) {
            BODY(eA, snA, rsA, rawA)
            BODY(eB, snB, rsB, rawB)
            nIter -= 2;
        }
        if (nIter) { BODY(eA, snA, rsA, rawA) }
    }
    // unpack accumulators, combine the 4 quarters
    float acc[8];
    unpk2(a2[0], acc[0], acc[1]);
    unpk2(a2[1], acc[2], acc[3]);
    unpk2(a2[2], acc[4], acc[5]);
    unpk2(a2[3], acc[6], acc[7]);
#pragma unroll
    for (int i = 0; i < 8; i++) {
        acc[i] += __shfl_xor_sync(FULL, acc[i], 8);
        acc[i] += __shfl_xor_sync(FULL, acc[i], 16);
    }
    ss += __shfl_xor_sync(FULL, ss, 8);
    ss += __shfl_xor_sync(FULL, ss, 16);
    float inv = (deg > 0) ? __frcp_rn(ss) : 0.0f;
    float ns = 0.0f;
#pragma unroll
    for (int i = 0; i < 8; i++) {
        acc[i] *= inv;
        ns = fmaf(acc[i], acc[i], ns);
    }
    ns += __shfl_xor_sync(FULL, ns, 1);
    ns += __shfl_xor_sync(FULL, ns, 2);
    ns += __shfl_xor_sync(FULL, ns, 4);
    if (qtr == 0) {
        uint4 r;
        __half2 p;
        p = __floats2half2_rn(acc[0], acc[1]); r.x = *reinterpret_cast<unsigned*>(&p);
        p = __floats2half2_rn(acc[2], acc[3]); r.y = *reinterpret_cast<unsigned*>(&p);
        p = __floats2half2_rn(acc[4], acc[5]); r.z = *reinterpret_cast<unsigned*>(&p);
        p = __floats2half2_rn(acc[6], acc[7]); r.w = *reinterpret_cast<unsigned*>(&p);
        *(uint4*)(out_h + node * HID + sub * 8) = r;
        if (sub == 0)
            rn_out[node] = L2E / fmaxf(sqrtf(ns), 1e-12f);
    }
}

// ---------------- launch 6: cls = h(fp16) @ W2 + b2, 32 rows/block ---------
__global__ __launch_bounds__(256) void cls_kernel(
    const __half* __restrict__ hh, const float* __restrict__ W2,
    const float* __restrict__ b2, float* __restrict__ out)
{
    __shared__ float sF[32][HID];         // 8 KB
    __shared__ float sWt[HID][68];        // 17.4 KB, padded
    int tid = threadIdx.x;
    int row0 = blockIdx.x * 32;
    for (int i = tid; i < 32 * HID; i += 256)
        sF[i >> 6][i & 63] = __half2float(hh[row0 * HID + i]);
    for (int i = tid; i < HID * HID; i += 256) {
        int k = i >> 6, j = i & 63;
        sWt[j][k] = W2[i];
    }
    __syncthreads();

    int r8 = tid >> 5, c = tid & 31;
    float bc0 = b2[c], bc1 = b2[c + 32];
    float a00 = bc0, a01 = bc1, a10 = bc0, a11 = bc1;
    float a20 = bc0, a21 = bc1, a30 = bc0, a31 = bc1;
#pragma unroll
    for (int k4 = 0; k4 < HID / 4; k4++) {
        float4 w0 = *(const float4*)&sWt[c     ][k4 * 4];
        float4 w1 = *(const float4*)&sWt[c + 32][k4 * 4];
        float4 f0 = *(const float4*)&sF[r8     ][k4 * 4];
        float4 f1 = *(const float4*)&sF[r8 +  8][k4 * 4];
        float4 f2 = *(const float4*)&sF[r8 + 16][k4 * 4];
        float4 f3 = *(const float4*)&sF[r8 + 24][k4 * 4];
        a00 = fmaf(f0.x, w0.x, a00); a00 = fmaf(f0.y, w0.y, a00);
        a00 = fmaf(f0.z, w0.z, a00); a00 = fmaf(f0.w, w0.w, a00);
        a01 = fmaf(f0.x, w1.x, a01); a01 = fmaf(f0.y, w1.y, a01);
        a01 = fmaf(f0.z, w1.z, a01); a01 = fmaf(f0.w, w1.w, a01);
        a10 = fmaf(f1.x, w0.x, a10); a10 = fmaf(f1.y, w0.y, a10);
        a10 = fmaf(f1.z, w0.z, a10); a10 = fmaf(f1.w, w0.w, a10);
        a11 = fmaf(f1.x, w1.x, a11); a11 = fmaf(f1.y, w1.y, a11);
        a11 = fmaf(f1.z, w1.z, a11); a11 = fmaf(f1.w, w1.w, a11);
        a20 = fmaf(f2.x, w0.x, a20); a20 = fmaf(f2.y, w0.y, a20);
        a20 = fmaf(f2.z, w0.z, a20); a20 = fmaf(f2.w, w0.w, a20);
        a21 = fmaf(f2.x, w1.x, a21); a21 = fmaf(f2.y, w1.y, a21);
        a21 = fmaf(f2.z, w1.z, a21); a21 = fmaf(f2.w, w1.w, a21);
        a30 = fmaf(f3.x, w0.x, a30); a30 = fmaf(f3.y, w0.y, a30);
        a30 = fmaf(f3.z, w0.z, a30); a30 = fmaf(f3.w, w0.w, a30);
        a31 = fmaf(f3.x, w1.x, a31); a31 = fmaf(f3.y, w1.y, a31);
        a31 = fmaf(f3.z, w1.z, a31); a31 = fmaf(f3.w, w1.w, a31);
    }
    out[(row0 + r8     ) * HID + c     ] = a00;
    out[(row0 + r8     ) * HID + c + 32] = a01;
    out[(row0 + r8 +  8) * HID + c     ] = a10;
    out[(row0 + r8 +  8) * HID + c + 32] = a11;
    out[(row0 + r8 + 16) * HID + c     ] = a20;
    out[(row0 + r8 + 16) * HID + c + 32] = a21;
    out[(row0 + r8 + 24) * HID + c     ] = a30;
    out[(row0 + r8 + 24) * HID + c + 32] = a31;
}

// ---------------------------------------------------------------------------
extern "C" void kernel_launch(void* const* d_in, const int* in_sizes, int n_in,
                              void* d_out, int out_size)
{
    const float* feat  = (const float*)d_in[0];
    const int*   src   = (const int*)  d_in[1];
    const int*   dst   = (const int*)  d_in[2];
    const float* W1    = (const float*)d_in[3];
    const float* b1    = (const float*)d_in[4];
    const float* W2    = (const float*)d_in[5];
    const float* b2    = (const float*)d_in[6];
    const float* betas = (const float*)d_in[7];

    __half *h0, *h1; float *rnA, *rnB; int *deg, *off, *cur, *bsum, *csr;
    cudaGetSymbolAddress((void**)&h0,   g_h0);
    cudaGetSymbolAddress((void**)&h1,   g_h1);
    cudaGetSymbolAddress((void**)&rnA,  g_rnA);
    cudaGetSymbolAddress((void**)&rnB,  g_rnB);
    cudaGetSymbolAddress((void**)&deg,  g_deg);
    cudaGetSymbolAddress((void**)&off,  g_off);
    cudaGetSymbolAddress((void**)&cur,  g_cur);
    cudaGetSymbolAddress((void**)&bsum, g_bsum);
    cudaGetSymbolAddress((void**)&csr,  g_csr);

    hist_kernel<<<N_EDGES / 8 / 256, 256>>>(dst, deg, bsum);
    scanF_kernel<<<N_NODES / 256, 256>>>(bsum, deg, off, cur);
    projscatter_kernel<<<N_NODES / 32, 256>>>(src, dst, cur, csr, bsum,
                                              feat, W1, b1, h0, rnA);
    layer_kernel<<<N_NODES * 32 / 256, 256>>>(csr, off, h0, rnA, betas, 0, h1, rnB);
    layer_kernel<<<N_NODES * 32 / 256, 256>>>(csr, off, h1, rnB, betas, 1, h0, rnA);
    cls_kernel<<<N_NODES / 32, 256>>>(h0, W2, b2, (float*)d_out);
}

// round 17
// speedup vs baseline: 1.0349x; 1.0349x over previous
#include <cuda_runtime.h>
#include <cuda_fp16.h>
#include <math_constants.h>

#define N_NODES 65536
#define N_EDGES 1048576
#define IN_F 128
#define HID 64
#define L2E 1.44269504088896f   // log2(e)
#define LN2 0.69314718055995f   // 1/log2(e)

// ---------------- scratch (device globals; no allocation allowed) ----------
__device__ __half g_h0[N_NODES * HID];  // 8 MB, fp16 node features ping
__device__ __half g_h1[N_NODES * HID];  // 8 MB, pong
__device__ float  g_rnA[N_NODES];       // log2e / max(||h||, eps)  (pre-scaled!)
__device__ float  g_rnB[N_NODES];       // pong
__device__ int    g_deg[N_NODES];       // zeroed by scanF each pass
__device__ int    g_off[N_NODES + 1];
__device__ int    g_cur[N_NODES];
__device__ int    g_bsum[256];          // chunk sums; zeroed by projscatter
__device__ int    g_csr[N_EDGES];       // src node id, grouped by dst

// ---------------- packed f32x2 helpers (sm_103a; inline PTX only) ----------
#define MUL2(d, a, b) \
    asm("mul.rn.f32x2 %0, %1, %2;" : "=l"(d) : "l"(a), "l"(b))
#define FMA2(d, a, b, c) \
    asm("fma.rn.f32x2 %0, %1, %2, %3;" : "=l"(d) : "l"(a), "l"(b), "l"(c))

__device__ __forceinline__ unsigned long long h2f2(unsigned h2v) {
    float2 t = __half22float2(*reinterpret_cast<const __half2*>(&h2v));
    unsigned long long p;
    asm("mov.b64 %0, {%1, %2};"
        : "=l"(p) : "r"(__float_as_uint(t.x)), "r"(__float_as_uint(t.y)));
    return p;
}
__device__ __forceinline__ void unpk2(unsigned long long p, float& lo, float& hi) {
    unsigned a, b;
    asm("mov.b64 {%0, %1}, %2;" : "=r"(a), "=r"(b) : "l"(p));
    lo = __uint_as_float(a); hi = __uint_as_float(b);
}
__device__ __forceinline__ float hadd2(unsigned long long p) {
    float lo, hi;
    unpk2(p, lo, hi);
    return lo + hi;
}
__device__ __forceinline__ float ex2f(float x) {
    float y;
    asm("ex2.approx.ftz.f32 %0, %1;" : "=f"(y) : "f"(x));
    return y;
}

// ---------------- launch 1: histogram, 8 edges/thread ----------------------
__global__ __launch_bounds__(256) void hist_kernel(
    const int* __restrict__ dst, int* __restrict__ deg, int* __restrict__ bsum)
{
    __shared__ int sc[256];
    int t = threadIdx.x;
    sc[t] = 0;
    __syncthreads();
    int i = blockIdx.x * 256 + t;
    int4 d0 = __ldg((const int4*)dst + 2 * i);
    int4 d1 = __ldg((const int4*)dst + 2 * i + 1);
    atomicAdd(deg + d0.x, 1); atomicAdd(deg + d0.y, 1);
    atomicAdd(deg + d0.z, 1); atomicAdd(deg + d0.w, 1);
    atomicAdd(deg + d1.x, 1); atomicAdd(deg + d1.y, 1);
    atomicAdd(deg + d1.z, 1); atomicAdd(deg + d1.w, 1);
    atomicAdd(sc + (d0.x >> 8), 1); atomicAdd(sc + (d0.y >> 8), 1);
    atomicAdd(sc + (d0.z >> 8), 1); atomicAdd(sc + (d0.w >> 8), 1);
    atomicAdd(sc + (d1.x >> 8), 1); atomicAdd(sc + (d1.y >> 8), 1);
    atomicAdd(sc + (d1.z >> 8), 1); atomicAdd(sc + (d1.w >> 8), 1);
    __syncthreads();
    int v = sc[t];
    if (v) atomicAdd(bsum + t, v);      // 256 spread addresses per block
}

// ---------------- launch 2: fused scan (block-local + chunk) + deg reset ---
__global__ __launch_bounds__(256) void scanF_kernel(
    const int* __restrict__ bsum, int* __restrict__ deg,
    int* __restrict__ off, int* __restrict__ cur)
{
    __shared__ int s[256];
    __shared__ int sb[256];
    int t = threadIdx.x;
    int b = blockIdx.x;
    int g = b * 256 + t;
    int d = deg[g];
    deg[g] = 0;                          // reset for next graph replay
    s[t]  = d;
    sb[t] = bsum[t];
    __syncthreads();
#pragma unroll
    for (int o = 1; o < 256; o <<= 1) {
        int v1 = (t >= o) ? s[t - o]  : 0;
        int v2 = (t >= o) ? sb[t - o] : 0;
        __syncthreads();
        s[t] += v1; sb[t] += v2;
        __syncthreads();
    }
    int excl_blk = sb[b] - bsum[b];      // exclusive chunk prefix
    int v = (s[t] - d) + excl_blk;       // global exclusive offset
    off[g] = v;
    cur[g] = v;
    if (g == 0) off[N_NODES] = N_EDGES;
}

// ---------------- launch 3: scatter (2 e/thread) + proj GEMM (32 rows) -----
// GEMM inner loop in packed f32x2 along K: both streams are pair-contiguous
// (sWt rows contiguous in k; feat rows contiguous) -> ulonglong2 vector loads
// feed FMA2 directly, no repacking. 16 FMA2 + 6 loads per k4 (was 32 FMA).
__global__ __launch_bounds__(256) void projscatter_kernel(
    const int* __restrict__ src, const int* __restrict__ dst,
    int* __restrict__ cur, int* __restrict__ csr, int* __restrict__ bsum,
    const float* __restrict__ feat, const float* __restrict__ W1,
    const float* __restrict__ b1, __half* __restrict__ out,
    float* __restrict__ rn)
{
    __shared__ float sWt[HID][132];       // 33.8 KB, padded (132 % 4 == 0)
    int tid = threadIdx.x;

    // --- scatter: 2 edges per thread (grid 2048 * 512 = N_EDGES) ---
    {
        int e0 = blockIdx.x * 512 + tid;
        int e1 = e0 + 256;
        int d0 = __ldg(dst + e0), d1 = __ldg(dst + e1);
        int v0 = __ldg(src + e0), v1 = __ldg(src + e1);
        int p0 = atomicAdd(cur + d0, 1);
        int p1 = atomicAdd(cur + d1, 1);
        csr[p0] = v0;
        csr[p1] = v1;
    }
    if (blockIdx.x == 0) bsum[tid] = 0;   // reset chunk sums for next replay

    // --- stage transposed W1 tile ---
    for (int i = tid; i < IN_F * HID; i += 256) {
        int k = i >> 6, j = i & 63;
        sWt[j][k] = W1[i];
    }
    __syncthreads();

    int row0 = blockIdx.x * 32;
    int r8 = tid >> 5, c = tid & 31;
    const ulonglong2* fr0 = (const ulonglong2*)(feat + (row0 + r8     ) * IN_F);
    const ulonglong2* fr1 = (const ulonglong2*)(feat + (row0 + r8 +  8) * IN_F);
    const ulonglong2* fr2 = (const ulonglong2*)(feat + (row0 + r8 + 16) * IN_F);
    const ulonglong2* fr3 = (const ulonglong2*)(feat + (row0 + r8 + 24) * IN_F);
    unsigned long long p00 = 0ull, p01 = 0ull, p10 = 0ull, p11 = 0ull;
    unsigned long long p20 = 0ull, p21 = 0ull, p30 = 0ull, p31 = 0ull;
#pragma unroll
    for (int k4 = 0; k4 < IN_F / 4; k4++) {
        ulonglong2 w0 = *(const ulonglong2*)&sWt[c     ][k4 * 4];
        ulonglong2 w1 = *(const ulonglong2*)&sWt[c + 32][k4 * 4];
        ulonglong2 f0 = __ldg(fr0 + k4);
        ulonglong2 f1 = __ldg(fr1 + k4);
        ulonglong2 f2 = __ldg(fr2 + k4);
        ulonglong2 f3 = __ldg(fr3 + k4);
        FMA2(p00, f0.x, w0.x, p00); FMA2(p00, f0.y, w0.y, p00);
        FMA2(p01, f0.x, w1.x, p01); FMA2(p01, f0.y, w1.y, p01);
        FMA2(p10, f1.x, w0.x, p10); FMA2(p10, f1.y, w0.y, p10);
        FMA2(p11, f1.x, w1.x, p11); FMA2(p11, f1.y, w1.y, p11);
        FMA2(p20, f2.x, w0.x, p20); FMA2(p20, f2.y, w0.y, p20);
        FMA2(p21, f2.x, w1.x, p21); FMA2(p21, f2.y, w1.y, p21);
        FMA2(p30, f3.x, w0.x, p30); FMA2(p30, f3.y, w0.y, p30);
        FMA2(p31, f3.x, w1.x, p31); FMA2(p31, f3.y, w1.y, p31);
    }
    float bc0 = b1[c], bc1 = b1[c + 32];
    float a00 = bc0 + hadd2(p00), a01 = bc1 + hadd2(p01);
    float a10 = bc0 + hadd2(p10), a11 = bc1 + hadd2(p11);
    float a20 = bc0 + hadd2(p20), a21 = bc1 + hadd2(p21);
    float a30 = bc0 + hadd2(p30), a31 = bc1 + hadd2(p31);
    a00 = fmaxf(a00, 0.0f); a01 = fmaxf(a01, 0.0f);
    a10 = fmaxf(a10, 0.0f); a11 = fmaxf(a11, 0.0f);
    a20 = fmaxf(a20, 0.0f); a21 = fmaxf(a21, 0.0f);
    a30 = fmaxf(a30, 0.0f); a31 = fmaxf(a31, 0.0f);
    out[(row0 + r8     ) * HID + c     ] = __float2half_rn(a00);
    out[(row0 + r8     ) * HID + c + 32] = __float2half_rn(a01);
    out[(row0 + r8 +  8) * HID + c     ] = __float2half_rn(a10);
    out[(row0 + r8 +  8) * HID + c + 32] = __float2half_rn(a11);
    out[(row0 + r8 + 16) * HID + c     ] = __float2half_rn(a20);
    out[(row0 + r8 + 16) * HID + c + 32] = __float2half_rn(a21);
    out[(row0 + r8 + 24) * HID + c     ] = __float2half_rn(a30);
    out[(row0 + r8 + 24) * HID + c + 32] = __float2half_rn(a31);
    float n0 = a00 * a00 + a01 * a01;
    float n1 = a10 * a10 + a11 * a11;
    float n2 = a20 * a20 + a21 * a21;
    float n3 = a30 * a30 + a31 * a31;
#pragma unroll
    for (int o = 16; o; o >>= 1) {
        n0 += __shfl_xor_sync(0xffffffffu, n0, o);
        n1 += __shfl_xor_sync(0xffffffffu, n1, o);
        n2 += __shfl_xor_sync(0xffffffffu, n2, o);
        n3 += __shfl_xor_sync(0xffffffffu, n3, o);
    }
    if (c == 0) {
        rn[row0 + r8     ] = L2E / fmaxf(sqrtf(n0), 1e-12f);
        rn[row0 + r8 +  8] = L2E / fmaxf(sqrtf(n1), 1e-12f);
        rn[row0 + r8 + 16] = L2E / fmaxf(sqrtf(n2), 1e-12f);
        rn[row0 + r8 + 24] = L2E / fmaxf(sqrtf(n3), 1e-12f);
    }
}

// ---------------- launches 4,5: fused AGNN layer (R14 best config) ---------
// Flat edge loop, per-quarter direct loads, 3 named pipeline slots at 4-edge
// granularity; dot and accumulate in packed f32x2 (FFMA2).
#define PREF(E, SN, RS, RAW)                                              \
    {                                                                     \
        int cidx = min(E, s1m1);                                          \
        SN = __ldg(csr + cidx);                                           \
        RS = __ldg(rn_in + SN);                                           \
        RAW = *(const uint4*)(hh + SN * HID + sub * 8);                   \
    }
#define BODY(E, SN, RS, RAW)                                              \
    {                                                                     \
        unsigned long long f0 = h2f2(RAW.x), f1 = h2f2(RAW.y);            \
        unsigned long long f2 = h2f2(RAW.z), f3 = h2f2(RAW.w);            \
        unsigned long long d2;                                            \
        MUL2(d2, q2[0], f0);                                              \
        FMA2(d2, q2[1], f1, d2);                                          \
        FMA2(d2, q2[2], f2, d2);                                          \
        FMA2(d2, q2[3], f3, d2);                                          \
        float dlo, dhi;                                                   \
        unpk2(d2, dlo, dhi);                                              \
        float dt = dlo + dhi;                                             \
        dt += __shfl_xor_sync(FULL, dt, 1);                               \
        dt += __shfl_xor_sync(FULL, dt, 2);                               \
        dt += __shfl_xor_sync(FULL, dt, 4);                               \
        float w = ex2f(fmaf(dt, RS, mB2));                                \
        w = (E < s1) ? w : 0.0f;                                          \
        ss += w;                                                          \
        unsigned long long w2;                                            \
        asm("mov.b64 %0, {%1, %1};" : "=l"(w2) : "r"(__float_as_uint(w)));\
        FMA2(a2[0], w2, f0, a2[0]);                                       \
        FMA2(a2[1], w2, f1, a2[1]);                                       \
        FMA2(a2[2], w2, f2, a2[2]);                                       \
        FMA2(a2[3], w2, f3, a2[3]);                                       \
        E += 12;                                                          \
        PREF(E, SN, RS, RAW)                                              \
    }

__global__ __launch_bounds__(256) void layer_kernel(
    const int* __restrict__ csr, const int* __restrict__ off,
    const __half* __restrict__ hh, const float* __restrict__ rn_in,
    const float* __restrict__ betas, int layer,
    __half* __restrict__ out_h, float* __restrict__ rn_out)
{
    int node = (blockIdx.x * blockDim.x + threadIdx.x) >> 5;
    int lane = threadIdx.x & 31;
    int qtr  = lane >> 3;
    int sub  = lane & 7;
    const unsigned FULL = 0xffffffffu;

    int s0 = off[node], s1 = off[node + 1];
    int deg = s1 - s0;
    int s1m1 = s1 - 1;
    float beta = __ldg(betas + layer);
    float mB2 = -fabsf(beta) * L2E;               // -log2e * max logit
    unsigned long long q2[4];
    {
        uint4 qraw = *(const uint4*)(hh + node * HID + sub * 8);
        float qs = beta * rn_in[node] * LN2;      // undo the log2e pre-scale
        unsigned long long qs2;
        asm("mov.b64 %0, {%1, %1};" : "=l"(qs2) : "r"(__float_as_uint(qs)));
        q2[0] = h2f2(qraw.x); MUL2(q2[0], q2[0], qs2);
        q2[1] = h2f2(qraw.y); MUL2(q2[1], q2[1], qs2);
        q2[2] = h2f2(qraw.z); MUL2(q2[2], q2[2], qs2);
        q2[3] = h2f2(qraw.w); MUL2(q2[3], q2[3], qs2);
    }

    float ss = 0.0f;
    unsigned long long a2[4] = {0ull, 0ull, 0ull, 0ull};  // packed (0.f, 0.f)

    if (deg > 0) {
        int eA = s0 + qtr, eB = eA + 4, eC = eA + 8;
        int snA, snB, snC; float rsA, rsB, rsC; uint4 rawA, rawB, rawC;
        PREF(eA, snA, rsA, rawA)
        PREF(eB, snB, rsB, rawB)
        PREF(eC, snC, rsC, rawC)
        int nIter = (deg + 3) >> 2;               // 4-edge chunks
        while (nIter >= 3) {
            BODY(eA, snA, rsA, rawA)
            BODY(eB, snB, rsB, rawB)
            BODY(eC, snC, rsC, rawC)
            nIter -= 3;
        }
        if (nIter >= 1) { BODY(eA, snA, rsA, rawA) }
        if (nIter == 2) { BODY(eB, snB, rsB, rawB) }
    }
    // unpack accumulators, combine the 4 quarters
    float acc[8];
    unpk2(a2[0], acc[0], acc[1]);
    unpk2(a2[1], acc[2], acc[3]);
    unpk2(a2[2], acc[4], acc[5]);
    unpk2(a2[3], acc[6], acc[7]);
#pragma unroll
    for (int i = 0; i < 8; i++) {
        acc[i] += __shfl_xor_sync(FULL, acc[i], 8);
        acc[i] += __shfl_xor_sync(FULL, acc[i], 16);
    }
    ss += __shfl_xor_sync(FULL, ss, 8);
    ss += __shfl_xor_sync(FULL, ss, 16);
    float inv = (deg > 0) ? __frcp_rn(ss) : 0.0f;
    float ns = 0.0f;
#pragma unroll
    for (int i = 0; i < 8; i++) {
        acc[i] *= inv;
        ns = fmaf(acc[i], acc[i], ns);
    }
    ns += __shfl_xor_sync(FULL, ns, 1);
    ns += __shfl_xor_sync(FULL, ns, 2);
    ns += __shfl_xor_sync(FULL, ns, 4);
    if (qtr == 0) {
        uint4 r;
        __half2 p;
        p = __floats2half2_rn(acc[0], acc[1]); r.x = *reinterpret_cast<unsigned*>(&p);
        p = __floats2half2_rn(acc[2], acc[3]); r.y = *reinterpret_cast<unsigned*>(&p);
        p = __floats2half2_rn(acc[4], acc[5]); r.z = *reinterpret_cast<unsigned*>(&p);
        p = __floats2half2_rn(acc[6], acc[7]); r.w = *reinterpret_cast<unsigned*>(&p);
        *(uint4*)(out_h + node * HID + sub * 8) = r;
        if (sub == 0)
            rn_out[node] = L2E / fmaxf(sqrtf(ns), 1e-12f);
    }
}

// ---------------- launch 6: cls = h(fp16) @ W2 + b2 (f32x2 packed K) -------
__global__ __launch_bounds__(256) void cls_kernel(
    const __half* __restrict__ hh, const float* __restrict__ W2,
    const float* __restrict__ b2, float* __restrict__ out)
{
    __shared__ float sF[32][HID];         // 8 KB
    __shared__ float sWt[HID][68];        // 17.4 KB, padded (68 % 4 == 0)
    int tid = threadIdx.x;
    int row0 = blockIdx.x * 32;
    for (int i = tid; i < 32 * HID; i += 256)
        sF[i >> 6][i & 63] = __half2float(hh[row0 * HID + i]);
    for (int i = tid; i < HID * HID; i += 256) {
        int k = i >> 6, j = i & 63;
        sWt[j][k] = W2[i];
    }
    __syncthreads();

    int r8 = tid >> 5, c = tid & 31;
    unsigned long long p00 = 0ull, p01 = 0ull, p10 = 0ull, p11 = 0ull;
    unsigned long long p20 = 0ull, p21 = 0ull, p30 = 0ull, p31 = 0ull;
#pragma unroll
    for (int k4 = 0; k4 < HID / 4; k4++) {
        ulonglong2 w0 = *(const ulonglong2*)&sWt[c     ][k4 * 4];
        ulonglong2 w1 = *(const ulonglong2*)&sWt[c + 32][k4 * 4];
        ulonglong2 f0 = *(const ulonglong2*)&sF[r8     ][k4 * 4];
        ulonglong2 f1 = *(const ulonglong2*)&sF[r8 +  8][k4 * 4];
        ulonglong2 f2 = *(const ulonglong2*)&sF[r8 + 16][k4 * 4];
        ulonglong2 f3 = *(const ulonglong2*)&sF[r8 + 24][k4 * 4];
        FMA2(p00, f0.x, w0.x, p00); FMA2(p00, f0.y, w0.y, p00);
        FMA2(p01, f0.x, w1.x, p01); FMA2(p01, f0.y, w1.y, p01);
        FMA2(p10, f1.x, w0.x, p10); FMA2(p10, f1.y, w0.y, p10);
        FMA2(p11, f1.x, w1.x, p11); FMA2(p11, f1.y, w1.y, p11);
        FMA2(p20, f2.x, w0.x, p20); FMA2(p20, f2.y, w0.y, p20);
        FMA2(p21, f2.x, w1.x, p21); FMA2(p21, f2.y, w1.y, p21);
        FMA2(p30, f3.x, w0.x, p30); FMA2(p30, f3.y, w0.y, p30);
        FMA2(p31, f3.x, w1.x, p31); FMA2(p31, f3.y, w1.y, p31);
    }
    float bc0 = b2[c], bc1 = b2[c + 32];
    out[(row0 + r8     ) * HID + c     ] = bc0 + hadd2(p00);
    out[(row0 + r8     ) * HID + c + 32] = bc1 + hadd2(p01);
    out[(row0 + r8 +  8) * HID + c     ] = bc0 + hadd2(p10);
    out[(row0 + r8 +  8) * HID + c + 32] = bc1 + hadd2(p11);
    out[(row0 + r8 + 16) * HID + c     ] = bc0 + hadd2(p20);
    out[(row0 + r8 + 16) * HID + c + 32] = bc1 + hadd2(p21);
    out[(row0 + r8 + 24) * HID + c     ] = bc0 + hadd2(p30);
    out[(row0 + r8 + 24) * HID + c + 32] = bc1 + hadd2(p31);
}

// ---------------------------------------------------------------------------
extern "C" void kernel_launch(void* const* d_in, const int* in_sizes, int n_in,
                              void* d_out, int out_size)
{
    const float* feat  = (const float*)d_in[0];
    const int*   src   = (const int*)  d_in[1];
    const int*   dst   = (const int*)  d_in[2];
    const float* W1    = (const float*)d_in[3];
    const float* b1    = (const float*)d_in[4];
    const float* W2    = (const float*)d_in[5];
    const float* b2    = (const float*)d_in[6];
    const float* betas = (const float*)d_in[7];

    __half *h0, *h1; float *rnA, *rnB; int *deg, *off, *cur, *bsum, *csr;
    cudaGetSymbolAddress((void**)&h0,   g_h0);
    cudaGetSymbolAddress((void**)&h1,   g_h1);
    cudaGetSymbolAddress((void**)&rnA,  g_rnA);
    cudaGetSymbolAddress((void**)&rnB,  g_rnB);
    cudaGetSymbolAddress((void**)&deg,  g_deg);
    cudaGetSymbolAddress((void**)&off,  g_off);
    cudaGetSymbolAddress((void**)&cur,  g_cur);
    cudaGetSymbolAddress((void**)&bsum, g_bsum);
    cudaGetSymbolAddress((void**)&csr,  g_csr);

    hist_kernel<<<N_EDGES / 8 / 256, 256>>>(dst, deg, bsum);
    scanF_kernel<<<N_NODES / 256, 256>>>(bsum, deg, off, cur);
    projscatter_kernel<<<N_NODES / 32, 256>>>(src, dst, cur, csr, bsum,
                                              feat, W1, b1, h0, rnA);
    layer_kernel<<<N_NODES * 32 / 256, 256>>>(csr, off, h0, rnA, betas, 0, h1, rnB);
    layer_kernel<<<N_NODES * 32 / 256, 256>>>(csr, off, h1, rnB, betas, 1, h0, rnA);
    cls_kernel<<<N_NODES / 32, 256>>>(h0, W2, b2, (float*)d_out);
}